// round 1
// baseline (speedup 1.0000x reference)
#include <cuda_runtime.h>
#include <cstddef>

// Problem constants
#define TA      262144      // T*A = 2048*128
#define A_DIM   128
#define D_OBS   64
#define NTP     4
#define DIN     68          // D_OBS + NTP
#define HDIM    64
#define NA      16
#define OUTC    17          // NA + 1 (value)
#define TILE    128         // rows per block
#define NTHR    256

// ---------------- scratch (static device globals; no allocation) ----------------
__device__ int g_perm[TA];
__device__ int g_cnt[NTP];
__device__ int g_off[NTP];
__device__ int g_cur[NTP];
__device__ int g_flag;      // 1 => hete_pick stored as int32, 0 => int64

// ---------------- prologue kernels ----------------
__global__ void k_init() {
    int t = threadIdx.x;
    if (t < NTP) g_cnt[t] = 0;
    if (t == NTP) g_flag = 0;
}

// Detect int32 vs int64 storage of hete_pick.
// Reading the first TA 32-bit words is safe in both cases. If the array is
// int64, every odd word is the (zero) high half. If int32, odd words are the
// picks of odd rows (131072 values in 0..3 -> some nonzero with certainty).
__global__ void k_detect(const int* __restrict__ h) {
    int stride = gridDim.x * blockDim.x;
    int acc = 0;
    for (int j = blockIdx.x * blockDim.x + threadIdx.x; j < TA / 2; j += stride)
        acc |= h[2 * j + 1];
    unsigned any = __ballot_sync(0xffffffffu, acc != 0);
    if ((threadIdx.x & 31) == 0 && any) atomicOr(&g_flag, 1);
}

__device__ __forceinline__ int pick_at(const int* __restrict__ h, int i, int f) {
    return f ? h[i] : h[2 * i];   // int64 little-endian: low word at 2*i
}

__global__ void k_count(const int* __restrict__ h) {
    __shared__ int sc[NTP];
    if (threadIdx.x < NTP) sc[threadIdx.x] = 0;
    __syncthreads();
    int f = g_flag;
    int stride = gridDim.x * blockDim.x;
    for (int i = blockIdx.x * blockDim.x + threadIdx.x; i < TA; i += stride)
        atomicAdd(&sc[pick_at(h, i, f)], 1);
    __syncthreads();
    if (threadIdx.x < NTP) atomicAdd(&g_cnt[threadIdx.x], sc[threadIdx.x]);
}

__global__ void k_offsets() {
    int o = 0;
    for (int e = 0; e < NTP; e++) { g_off[e] = o; g_cur[e] = o; o += g_cnt[e]; }
}

// 512 blocks x 512 rows each: block-aggregated scatter into per-expert buckets.
__global__ void k_scatter(const int* __restrict__ h) {
    __shared__ int sHist[NTP], sBase[NTP], sRank[NTP];
    int tid = threadIdx.x;
    if (tid < NTP) { sHist[tid] = 0; sRank[tid] = 0; }
    __syncthreads();
    int f = g_flag;
    int r0 = blockIdx.x * 512;
    int i0 = r0 + tid;
    int i1 = r0 + 256 + tid;
    int t0 = pick_at(h, i0, f);
    int t1 = pick_at(h, i1, f);
    atomicAdd(&sHist[t0], 1);
    atomicAdd(&sHist[t1], 1);
    __syncthreads();
    if (tid < NTP) sBase[tid] = atomicAdd(&g_cur[tid], sHist[tid]);
    __syncthreads();
    int p0 = atomicAdd(&sRank[t0], 1);
    g_perm[sBase[t0] + p0] = i0;
    int p1 = atomicAdd(&sRank[t1], 1);
    g_perm[sBase[t1] + p1] = i1;
}

// ---------------- fused 3-layer MLP tile kernel ----------------
// Shared layout (in floats)
#define OFF_W1   0                         // [68][64]
#define OFF_W2   (OFF_W1 + DIN * HDIM)     // 4352  [64][64]
#define OFF_W3   (OFF_W2 + HDIM * HDIM)    // 8448  [64][16] (critic uses 64)
#define OFF_B1   (OFF_W3 + HDIM * NA)      // 9472
#define OFF_B2   (OFF_B1 + HDIM)           // 9536
#define OFF_B3   (OFF_B2 + HDIM)           // 9600
#define OFF_X    (OFF_B3 + 16)             // 9616  [128][68]
#define OFF_H1   (OFF_X + TILE * DIN)      // 18320 [128][64]
#define OFF_ROWS (OFF_H1 + TILE * HDIM)    // 26512 (ints)
#define SMEM_FLOATS (OFF_ROWS + TILE)      // 26640
#define SMEM_BYTES  (SMEM_FLOATS * 4)      // 106560

extern __shared__ float smem[];

// One tile layer: out[128][64] = act(in[128][KD] @ W[KD][64] + b)
// 256 threads: tc = tid&15 -> 4 cols, tr = tid>>4 -> 8 rows. 8x4 micro-tile.
template <int KD, int LDI, bool RELU>
__device__ __forceinline__ void layer64(const float* __restrict__ sIn,
                                        const float* __restrict__ sW,
                                        const float* __restrict__ sB,
                                        float* __restrict__ sOut, int tid) {
    const int tc = tid & 15;
    const int tr = tid >> 4;
    float acc[8][4];
#pragma unroll
    for (int r = 0; r < 8; r++)
#pragma unroll
        for (int c = 0; c < 4; c++) acc[r][c] = 0.0f;

    for (int k = 0; k < KD; k += 4) {
        float xb[8][4];
#pragma unroll
        for (int r = 0; r < 8; r++) {
            float4 v = *(const float4*)&sIn[(tr * 8 + r) * LDI + k];
            xb[r][0] = v.x; xb[r][1] = v.y; xb[r][2] = v.z; xb[r][3] = v.w;
        }
#pragma unroll
        for (int kk = 0; kk < 4; kk++) {
            float4 w = *(const float4*)&sW[(k + kk) * HDIM + tc * 4];
#pragma unroll
            for (int r = 0; r < 8; r++) {
                acc[r][0] += xb[r][kk] * w.x;
                acc[r][1] += xb[r][kk] * w.y;
                acc[r][2] += xb[r][kk] * w.z;
                acc[r][3] += xb[r][kk] * w.w;
            }
        }
    }
    float4 b = *(const float4*)&sB[tc * 4];
#pragma unroll
    for (int r = 0; r < 8; r++) {
        float4 o;
        o.x = acc[r][0] + b.x;
        o.y = acc[r][1] + b.y;
        o.z = acc[r][2] + b.z;
        o.w = acc[r][3] + b.w;
        if (RELU) {
            o.x = fmaxf(o.x, 0.0f); o.y = fmaxf(o.y, 0.0f);
            o.z = fmaxf(o.z, 0.0f); o.w = fmaxf(o.w, 0.0f);
        }
        *(float4*)&sOut[(tr * 8 + r) * HDIM + tc * 4] = o;
    }
}

__global__ void __launch_bounds__(NTHR, 2) mlp_kernel(
    const float* __restrict__ obs, const float* __restrict__ gp,
    const float* __restrict__ W1, const float* __restrict__ b1,
    const float* __restrict__ W2, const float* __restrict__ b2,
    const float* __restrict__ W3, const float* __restrict__ b3,
    const float* __restrict__ cW1, const float* __restrict__ cb1,
    const float* __restrict__ cW2, const float* __restrict__ cb2,
    const float* __restrict__ cW3, const float* __restrict__ cb3,
    float* __restrict__ out) {
    float* sW1 = smem + OFF_W1;
    float* sW2 = smem + OFF_W2;
    float* sW3 = smem + OFF_W3;
    float* sB1 = smem + OFF_B1;
    float* sB2 = smem + OFF_B2;
    float* sB3 = smem + OFF_B3;
    float* sX  = smem + OFF_X;
    float* sH1 = smem + OFF_H1;
    float* sH2 = sX;  // reuse X buffer after layer 1
    int*   sRows = (int*)(smem + OFF_ROWS);

    const int e = blockIdx.y;
    const bool critic = (e == NTP);
    const int tid = threadIdx.x;
    const int start = blockIdx.x * TILE;

    int nvalid = TILE;
    int base = 0;
    if (!critic) {
        int cnt = g_cnt[e];
        if (start >= cnt) return;          // uniform across block: safe
        nvalid = min(TILE, cnt - start);
        base = g_off[e];
    }

    // row indices for this tile (invalid slots -> row 0, stores are guarded)
    if (tid < TILE) {
        int row;
        if (critic) row = start + tid;
        else row = (tid < nvalid) ? g_perm[base + start + tid] : 0;
        sRows[tid] = row;
    }

    // stage weights
    const float* w1p = critic ? cW1 : (W1 + (size_t)e * DIN * HDIM);
    const float* w2p = critic ? cW2 : (W2 + (size_t)e * HDIM * HDIM);
    const float* w3p = critic ? cW3 : (W3 + (size_t)e * HDIM * NA);
    const float* b1p = critic ? cb1 : (b1 + e * HDIM);
    const float* b2p = critic ? cb2 : (b2 + e * HDIM);
    for (int i = tid; i < DIN * HDIM; i += NTHR) sW1[i] = w1p[i];
    for (int i = tid; i < HDIM * HDIM; i += NTHR) sW2[i] = w2p[i];
    {
        int nw3 = critic ? HDIM : HDIM * NA;
        for (int i = tid; i < nw3; i += NTHR) sW3[i] = w3p[i];
    }
    if (tid < HDIM) { sB1[tid] = b1p[tid]; sB2[tid] = b2p[tid]; }
    if (tid < NA) sB3[tid] = critic ? ((tid == 0) ? cb3[0] : 0.0f) : b3[e * NA + tid];
    __syncthreads();

    // stage X tile: [r][0..63] = obs row, [r][64..67] = gp_sel_summary[t]
    for (int idx = tid; idx < TILE * 16; idx += NTHR) {
        int r = idx >> 4, q = idx & 15;
        float4 v = *(const float4*)(obs + (size_t)sRows[r] * D_OBS + q * 4);
        *(float4*)&sX[r * DIN + q * 4] = v;
    }
    if (tid < TILE) {
        int t = sRows[tid] >> 7;  // row / A_DIM
        *(float4*)&sX[tid * DIN + D_OBS] = *(const float4*)(gp + t * NTP);
    }
    __syncthreads();

    layer64<DIN, DIN, true>(sX, sW1, sB1, sH1, tid);
    __syncthreads();
    layer64<HDIM, HDIM, true>(sH1, sW2, sB2, sH2, tid);
    __syncthreads();

    if (!critic) {
        // logits: [128 rows][16 cols]; thread: col c, 8 rows
        const int c = tid & 15;
        const int r0 = (tid >> 4) * 8;
        float a[8];
#pragma unroll
        for (int r = 0; r < 8; r++) a[r] = 0.0f;
        for (int k = 0; k < HDIM; k += 4) {
            float wv0 = sW3[(k + 0) * NA + c];
            float wv1 = sW3[(k + 1) * NA + c];
            float wv2 = sW3[(k + 2) * NA + c];
            float wv3 = sW3[(k + 3) * NA + c];
#pragma unroll
            for (int r = 0; r < 8; r++) {
                float4 h = *(const float4*)&sH2[(r0 + r) * HDIM + k];
                a[r] += h.x * wv0 + h.y * wv1 + h.z * wv2 + h.w * wv3;
            }
        }
        float bc = sB3[c];
#pragma unroll
        for (int r = 0; r < 8; r++) {
            if (r0 + r < nvalid)
                out[(size_t)sRows[r0 + r] * OUTC + c] = a[r] + bc;
        }
    } else {
        // value column: 128 rows, 1 col; 2 threads per row
        const int r = tid >> 1;
        const int p = tid & 1;
        float a = 0.0f;
        for (int kk = 0; kk < 32; kk += 4) {
            int k = p * 32 + kk;
            float4 h = *(const float4*)&sH2[r * HDIM + k];
            a += h.x * sW3[k] + h.y * sW3[k + 1] + h.z * sW3[k + 2] + h.w * sW3[k + 3];
        }
        a += __shfl_xor_sync(0xffffffffu, a, 1);
        if (p == 0)
            out[(size_t)(start + r) * OUTC + NA] = a + sB3[0];
    }
}

// ---------------- launch ----------------
extern "C" void kernel_launch(void* const* d_in, const int* in_sizes, int n_in,
                              void* d_out, int out_size) {
    const float* obs  = (const float*)d_in[0];
    const int*   hete = (const int*)d_in[1];
    const float* gp   = (const float*)d_in[2];
    const float* W1   = (const float*)d_in[3];
    const float* b1   = (const float*)d_in[4];
    const float* W2   = (const float*)d_in[5];
    const float* b2   = (const float*)d_in[6];
    const float* W3   = (const float*)d_in[7];
    const float* b3   = (const float*)d_in[8];
    const float* cW1  = (const float*)d_in[9];
    const float* cb1  = (const float*)d_in[10];
    const float* cW2  = (const float*)d_in[11];
    const float* cb2  = (const float*)d_in[12];
    const float* cW3  = (const float*)d_in[13];
    const float* cb3  = (const float*)d_in[14];
    float* out = (float*)d_out;

    cudaFuncSetAttribute(mlp_kernel, cudaFuncAttributeMaxDynamicSharedMemorySize,
                         SMEM_BYTES);

    k_init<<<1, 32>>>();
    k_detect<<<256, 256>>>(hete);
    k_count<<<256, 256>>>(hete);
    k_offsets<<<1, 1>>>();
    k_scatter<<<512, 256>>>(hete);

    dim3 grid(TA / TILE, NTP + 1);   // y: 0..3 experts, 4 critic
    mlp_kernel<<<grid, NTHR, SMEM_BYTES>>>(obs, gp, W1, b1, W2, b2, W3, b3,
                                           cW1, cb1, cW2, cb2, cW3, cb3, out);
}

// round 2
// speedup vs baseline: 1.2151x; 1.2151x over previous
#include <cuda_runtime.h>
#include <cstddef>

// Problem constants
#define TA      262144      // T*A = 2048*128
#define D_OBS   64
#define NTP     4
#define DIN     68          // D_OBS + NTP
#define HDIM    64
#define NA      16
#define OUTC    17          // NA + 1 (value)
#define TILE    128         // rows per block
#define NTHR    256

// ---------------- scratch (static device globals; no allocation) ----------------
__device__ int g_perm[NTP * TA];   // per-expert buckets at base e*TA
__device__ int g_cnt[NTP];
__device__ int g_flag;             // 1 => hete_pick stored as int32, 0 => int64

// ---------------- f32x2 helpers ----------------
#define FMA2(acc, a, b) \
    asm("fma.rn.f32x2 %0, %1, %2, %0;" : "+l"(acc) : "l"(a), "l"(b))
#define PACK_DUP(d, x) \
    asm("mov.b64 %0, {%1, %1};" : "=l"(d) : "r"(__float_as_uint(x)))
#define PACK2(d, x, y) \
    asm("mov.b64 %0, {%1, %2};" : "=l"(d) : "r"(__float_as_uint(x)), "r"(__float_as_uint(y)))
#define ADD2(d, a, b) \
    asm("add.rn.f32x2 %0, %1, %2;" : "=l"(d) : "l"(a), "l"(b))
#define UNPACK2(lo, hi, v) \
    asm("mov.b64 {%0, %1}, %2;" : "=r"(lo), "=r"(hi) : "l"(v))

typedef unsigned long long u64;

// ---------------- prologue kernels ----------------
__global__ void k_init() {
    int t = threadIdx.x;
    if (t < NTP) g_cnt[t] = 0;
    if (t == NTP) g_flag = 0;
}

// Detect int32 vs int64 storage of hete_pick: if int64 (little-endian), every
// odd 32-bit word is the zero high half; if int32, odd words hold picks of odd
// rows (131072 uniform values in 0..3 -> certainly some nonzero).
__global__ void k_detect(const int* __restrict__ h) {
    int stride = gridDim.x * blockDim.x;
    int acc = 0;
    for (int j = blockIdx.x * blockDim.x + threadIdx.x; j < TA / 2; j += stride)
        acc |= h[2 * j + 1];
    unsigned any = __ballot_sync(0xffffffffu, acc != 0);
    if ((threadIdx.x & 31) == 0 && any) atomicOr(&g_flag, 1);
}

__device__ __forceinline__ int pick_at(const int* __restrict__ h, int i, int f) {
    return f ? h[i] : h[2 * i];   // int64 little-endian: low word at 2*i
}

// Block-aggregated classify+scatter into per-expert buckets (no prefix pass).
__global__ void k_build(const int* __restrict__ h) {
    __shared__ int sHist[NTP], sBase[NTP], sRank[NTP];
    int tid = threadIdx.x;
    if (tid < NTP) { sHist[tid] = 0; sRank[tid] = 0; }
    __syncthreads();
    int f = g_flag;
    int i = blockIdx.x * 512 + tid;
    int t = pick_at(h, i, f);
    atomicAdd(&sHist[t], 1);
    __syncthreads();
    if (tid < NTP) sBase[tid] = atomicAdd(&g_cnt[tid], sHist[tid]);
    __syncthreads();
    int p = atomicAdd(&sRank[t], 1);
    g_perm[t * TA + sBase[t] + p] = i;
}

// ---------------- fused 3-layer MLP tile kernel ----------------
// Shared layout (in floats)
#define OFF_W1   0                         // [68][64]
#define OFF_W2   (OFF_W1 + DIN * HDIM)     // 4352  [64][64]
#define OFF_W3   (OFF_W2 + HDIM * HDIM)    // 8448  [64][16] (critic uses 64)
#define OFF_B1   (OFF_W3 + HDIM * NA)      // 9472
#define OFF_B2   (OFF_B1 + HDIM)           // 9536
#define OFF_B3   (OFF_B2 + HDIM)           // 9600
#define OFF_X    (OFF_B3 + 16)             // 9616  [128][68]
#define OFF_H1   (OFF_X + TILE * DIN)      // 18320 [128][64]
#define OFF_ROWS (OFF_H1 + TILE * HDIM)    // 26512 (ints)
#define SMEM_FLOATS (OFF_ROWS + TILE)      // 26640
#define SMEM_BYTES  (SMEM_FLOATS * 4)      // 106560

extern __shared__ float smem[];

// out[128][64] = act(in[128][KD] @ W[KD][64] + b) with packed-f32x2 columns.
// 256 threads: tc = tid&15 -> cols tc*4..tc*4+3 (as 2 f32x2 pairs), tr = tid>>4 -> 8 rows.
template <int KD, int LDI, bool RELU>
__device__ __forceinline__ void layer64(const float* __restrict__ sIn,
                                        const float* __restrict__ sW,
                                        const float* __restrict__ sB,
                                        float* __restrict__ sOut, int tid) {
    const int tc = tid & 15;
    const int tr = tid >> 4;
    u64 acc0[8], acc1[8];
#pragma unroll
    for (int r = 0; r < 8; r++) { acc0[r] = 0ull; acc1[r] = 0ull; }

    const float* inBase = sIn + (tr * 8) * LDI;
    const float* wBase  = sW + tc * 4;

    for (int k = 0; k < KD; k += 4) {
        float4 xv[8];
#pragma unroll
        for (int r = 0; r < 8; r++)
            xv[r] = *(const float4*)&inBase[r * LDI + k];
#pragma unroll
        for (int kk = 0; kk < 4; kk++) {
            ulonglong2 w = *(const ulonglong2*)&wBase[(k + kk) * HDIM];
#pragma unroll
            for (int r = 0; r < 8; r++) {
                float xs = (kk == 0) ? xv[r].x : (kk == 1) ? xv[r].y
                         : (kk == 2) ? xv[r].z : xv[r].w;
                u64 bx;
                PACK_DUP(bx, xs);
                FMA2(acc0[r], bx, w.x);
                FMA2(acc1[r], bx, w.y);
            }
        }
    }

    ulonglong2 b = *(const ulonglong2*)&sB[tc * 4];
#pragma unroll
    for (int r = 0; r < 8; r++) {
        u64 s0, s1;
        ADD2(s0, acc0[r], b.x);
        ADD2(s1, acc1[r], b.y);
        unsigned u0, u1, u2, u3;
        UNPACK2(u0, u1, s0);
        UNPACK2(u2, u3, s1);
        float4 o;
        o.x = __uint_as_float(u0); o.y = __uint_as_float(u1);
        o.z = __uint_as_float(u2); o.w = __uint_as_float(u3);
        if (RELU) {
            o.x = fmaxf(o.x, 0.0f); o.y = fmaxf(o.y, 0.0f);
            o.z = fmaxf(o.z, 0.0f); o.w = fmaxf(o.w, 0.0f);
        }
        *(float4*)&sOut[(tr * 8 + r) * HDIM + tc * 4] = o;
    }
}

__global__ void __launch_bounds__(NTHR, 2) mlp_kernel(
    const float* __restrict__ obs, const float* __restrict__ gp,
    const float* __restrict__ W1, const float* __restrict__ b1,
    const float* __restrict__ W2, const float* __restrict__ b2,
    const float* __restrict__ W3, const float* __restrict__ b3,
    const float* __restrict__ cW1, const float* __restrict__ cb1,
    const float* __restrict__ cW2, const float* __restrict__ cb2,
    const float* __restrict__ cW3, const float* __restrict__ cb3,
    float* __restrict__ out) {
    float* sW1 = smem + OFF_W1;
    float* sW2 = smem + OFF_W2;
    float* sW3 = smem + OFF_W3;
    float* sB1 = smem + OFF_B1;
    float* sB2 = smem + OFF_B2;
    float* sB3 = smem + OFF_B3;
    float* sX  = smem + OFF_X;
    float* sH1 = smem + OFF_H1;
    float* sH2 = sX;  // reuse X buffer after layer 1
    int*   sRows = (int*)(smem + OFF_ROWS);

    const int e = blockIdx.y;
    const bool critic = (e == NTP);
    const int tid = threadIdx.x;
    const int start = blockIdx.x * TILE;

    int nvalid = TILE;
    if (!critic) {
        int cnt = g_cnt[e];
        if (start >= cnt) return;          // uniform across block: safe
        nvalid = min(TILE, cnt - start);
    }

    // row indices for this tile (invalid slots -> row 0, stores are guarded)
    if (tid < TILE) {
        int row;
        if (critic) row = start + tid;
        else row = (tid < nvalid) ? g_perm[e * TA + start + tid] : 0;
        sRows[tid] = row;
    }

    // stage weights
    const float* w1p = critic ? cW1 : (W1 + (size_t)e * DIN * HDIM);
    const float* w2p = critic ? cW2 : (W2 + (size_t)e * HDIM * HDIM);
    const float* w3p = critic ? cW3 : (W3 + (size_t)e * HDIM * NA);
    const float* b1p = critic ? cb1 : (b1 + e * HDIM);
    const float* b2p = critic ? cb2 : (b2 + e * HDIM);
    for (int i = tid; i < DIN * HDIM; i += NTHR) sW1[i] = w1p[i];
    for (int i = tid; i < HDIM * HDIM; i += NTHR) sW2[i] = w2p[i];
    {
        int nw3 = critic ? HDIM : HDIM * NA;
        for (int i = tid; i < nw3; i += NTHR) sW3[i] = w3p[i];
    }
    if (tid < HDIM) { sB1[tid] = b1p[tid]; sB2[tid] = b2p[tid]; }
    if (tid < NA) sB3[tid] = critic ? ((tid == 0) ? cb3[0] : 0.0f) : b3[e * NA + tid];
    __syncthreads();

    // stage X tile: [r][0..63] = obs row, [r][64..67] = gp_sel_summary[t]
    for (int idx = tid; idx < TILE * 16; idx += NTHR) {
        int r = idx >> 4, q = idx & 15;
        float4 v = *(const float4*)(obs + (size_t)sRows[r] * D_OBS + q * 4);
        *(float4*)&sX[r * DIN + q * 4] = v;
    }
    if (tid < TILE) {
        int t = sRows[tid] >> 7;  // row / A_DIM (A=128)
        *(float4*)&sX[tid * DIN + D_OBS] = *(const float4*)(gp + t * NTP);
    }
    __syncthreads();

    layer64<DIN, DIN, true>(sX, sW1, sB1, sH1, tid);
    __syncthreads();
    layer64<HDIM, HDIM, true>(sH1, sW2, sB2, sH2, tid);
    __syncthreads();

    if (!critic) {
        // logits: [128 rows][16 cols]; thread: col c, 8 rows.
        // Packed over k parity: acc lanes = (even-k partial, odd-k partial).
        const int c = tid & 15;
        const int r0 = (tid >> 4) * 8;
        u64 acc[8];
#pragma unroll
        for (int r = 0; r < 8; r++) acc[r] = 0ull;
        for (int k = 0; k < HDIM; k += 4) {
            u64 w01, w23;
            PACK2(w01, sW3[(k + 0) * NA + c], sW3[(k + 1) * NA + c]);
            PACK2(w23, sW3[(k + 2) * NA + c], sW3[(k + 3) * NA + c]);
#pragma unroll
            for (int r = 0; r < 8; r++) {
                ulonglong2 h = *(const ulonglong2*)&sH2[(r0 + r) * HDIM + k];
                FMA2(acc[r], h.x, w01);
                FMA2(acc[r], h.y, w23);
            }
        }
        float bc = sB3[c];
#pragma unroll
        for (int r = 0; r < 8; r++) {
            unsigned lo, hi;
            UNPACK2(lo, hi, acc[r]);
            float a = __uint_as_float(lo) + __uint_as_float(hi) + bc;
            if (r0 + r < nvalid)
                out[(size_t)sRows[r0 + r] * OUTC + c] = a;
        }
    } else {
        // value column: 128 rows, 1 col; 2 threads per row
        const int r = tid >> 1;
        const int p = tid & 1;
        u64 acc = 0ull;
        for (int kk = 0; kk < 32; kk += 4) {
            int k = p * 32 + kk;
            ulonglong2 h = *(const ulonglong2*)&sH2[r * HDIM + k];
            ulonglong2 w = *(const ulonglong2*)&sW3[k];
            FMA2(acc, h.x, w.x);
            FMA2(acc, h.y, w.y);
        }
        unsigned lo, hi;
        UNPACK2(lo, hi, acc);
        float a = __uint_as_float(lo) + __uint_as_float(hi);
        a += __shfl_xor_sync(0xffffffffu, a, 1);
        if (p == 0)
            out[(size_t)(start + r) * OUTC + NA] = a + sB3[0];
    }
}

// ---------------- launch ----------------
extern "C" void kernel_launch(void* const* d_in, const int* in_sizes, int n_in,
                              void* d_out, int out_size) {
    const float* obs  = (const float*)d_in[0];
    const int*   hete = (const int*)d_in[1];
    const float* gp   = (const float*)d_in[2];
    const float* W1   = (const float*)d_in[3];
    const float* b1   = (const float*)d_in[4];
    const float* W2   = (const float*)d_in[5];
    const float* b2   = (const float*)d_in[6];
    const float* W3   = (const float*)d_in[7];
    const float* b3   = (const float*)d_in[8];
    const float* cW1  = (const float*)d_in[9];
    const float* cb1  = (const float*)d_in[10];
    const float* cW2  = (const float*)d_in[11];
    const float* cb2  = (const float*)d_in[12];
    const float* cW3  = (const float*)d_in[13];
    const float* cb3  = (const float*)d_in[14];
    float* out = (float*)d_out;

    cudaFuncSetAttribute(mlp_kernel, cudaFuncAttributeMaxDynamicSharedMemorySize,
                         SMEM_BYTES);

    k_init<<<1, 32>>>();
    k_detect<<<128, 256>>>(hete);
    k_build<<<TA / 512, 512>>>(hete);

    dim3 grid(TA / TILE, NTP + 1);   // y: 0..3 experts, 4 critic
    mlp_kernel<<<grid, NTHR, SMEM_BYTES>>>(obs, gp, W1, b1, W2, b2, W3, b3,
                                           cW1, cb1, cW2, cb2, cW3, cb3, out);
}

// round 3
// speedup vs baseline: 1.2615x; 1.0382x over previous
#include <cuda_runtime.h>
#include <cstddef>

// Problem constants
#define TA      262144      // T*A = 2048*128
#define D_OBS   64
#define NTP     4
#define DIN     68          // D_OBS + NTP
#define HDIM    64
#define NA      16
#define OUTC    17          // NA + 1 (value)
#define TILE    128         // rows per tile
#define NTHR    256
#define NCTA    296         // persistent CTAs (2 per SM on 148 SMs)
#define ECTAS   37          // CTAs per expert (4*37 = 148)

#define WS1     70          // W1T row stride (K=68, stride ≡ 2 mod 4)
#define WS      66          // W2T/W3T row stride (K=64)

// ---------------- scratch ----------------
__device__ int g_perm[NTP * TA];   // per-expert buckets at base e*TA
__device__ int g_cnt[NTP];
__device__ int g_flag;             // 1 => hete_pick stored as int32, 0 => int64

// ---------------- f32x2 helpers ----------------
#define FMA2(acc, a, b) \
    asm("fma.rn.f32x2 %0, %1, %2, %0;" : "+l"(acc) : "l"(a), "l"(b))
#define UNPACK2(lo, hi, v) \
    asm("mov.b64 {%0, %1}, %2;" : "=r"(lo), "=r"(hi) : "l"(v))

typedef unsigned long long u64;

// ---------------- prologue kernels ----------------
__global__ void k_init() {
    int t = threadIdx.x;
    if (t < NTP) g_cnt[t] = 0;
    if (t == NTP) g_flag = 0;
}

// Detect int32 vs int64 storage of hete_pick (int64 LE: odd words all zero).
__global__ void k_detect(const int* __restrict__ h) {
    int stride = gridDim.x * blockDim.x;
    int acc = 0;
    for (int j = blockIdx.x * blockDim.x + threadIdx.x; j < TA / 2; j += stride)
        acc |= h[2 * j + 1];
    unsigned any = __ballot_sync(0xffffffffu, acc != 0);
    if ((threadIdx.x & 31) == 0 && any) atomicOr(&g_flag, 1);
}

__device__ __forceinline__ int pick_at(const int* __restrict__ h, int i, int f) {
    return f ? h[i] : h[2 * i];
}

// Block-aggregated classify+scatter into per-expert buckets.
__global__ void k_build(const int* __restrict__ h) {
    __shared__ int sHist[NTP], sBase[NTP], sRank[NTP];
    int tid = threadIdx.x;
    if (tid < NTP) { sHist[tid] = 0; sRank[tid] = 0; }
    __syncthreads();
    int f = g_flag;
    int i = blockIdx.x * 512 + tid;
    int t = pick_at(h, i, f);
    atomicAdd(&sHist[t], 1);
    __syncthreads();
    if (tid < NTP) sBase[tid] = atomicAdd(&g_cnt[tid], sHist[tid]);
    __syncthreads();
    int p = atomicAdd(&sRank[t], 1);
    g_perm[t * TA + sBase[t] + p] = i;
}

// ---------------- shared layout (floats) ----------------
#define OFF_W1T  0                          // [64 cols][70]
#define OFF_W2T  (OFF_W1T + 64 * WS1)       // 4480  [64 cols][66]
#define OFF_W3T  (OFF_W2T + 64 * WS)        // 8704  [16 cols][66]
#define OFF_VW   (OFF_W3T + 16 * WS)        // 9760  critic W3 vector [64]
#define OFF_B1   (OFF_VW + 64)              // 9824
#define OFF_B2   (OFF_B1 + 64)              // 9888
#define OFF_B3   (OFF_B2 + 64)              // 9952
#define OFF_VB   (OFF_B3 + 16)              // 9968
#define OFF_X    (OFF_VB + 4)               // 9972  [128][68]
#define OFF_H1   (OFF_X + TILE * DIN)       // 18676 [128][64]
#define OFF_ROWS (OFF_H1 + TILE * HDIM)     // 26868 (ints)
#define SMEM_FLOATS (OFF_ROWS + TILE)       // 26996
#define SMEM_BYTES  (SMEM_FLOATS * 4)       // 107984

extern __shared__ float smem[];

// out[128][HDIM] = act(in[128][KD] @ W + b), W transposed in smem: sWT[c][k].
// f32x2 lanes = (even-k partial, odd-k partial) of one output -> no packing movs.
// 256 threads: tc = tid&15 -> cols {tc, tc+16, tc+32, tc+48}; tr = tid>>4 -> 8 rows.
template <int KD, int LDI, int WSTR, bool RELU>
__device__ __forceinline__ void layerT(const float* __restrict__ sIn,
                                       const float* __restrict__ sWT,
                                       const float* __restrict__ sB,
                                       float* __restrict__ sOut, int tid) {
    const int tc = tid & 15;
    const int tr = tid >> 4;
    u64 acc[8][4];
#pragma unroll
    for (int r = 0; r < 8; r++)
#pragma unroll
        for (int i = 0; i < 4; i++) acc[r][i] = 0ull;

    const float* inB = sIn + (tr * 8) * LDI;

    for (int k = 0; k < KD; k += 4) {
        ulonglong2 xv[8];   // xv[r].x = (x[k],x[k+1]), .y = (x[k+2],x[k+3])
#pragma unroll
        for (int r = 0; r < 8; r++)
            xv[r] = *(const ulonglong2*)&inB[r * LDI + k];
#pragma unroll
        for (int i = 0; i < 4; i++) {
            const float* wc = sWT + (tc + 16 * i) * WSTR + k;
            u64 w01 = *(const u64*)&wc[0];
            u64 w23 = *(const u64*)&wc[2];
#pragma unroll
            for (int r = 0; r < 8; r++) {
                FMA2(acc[r][i], xv[r].x, w01);
                FMA2(acc[r][i], xv[r].y, w23);
            }
        }
    }
#pragma unroll
    for (int i = 0; i < 4; i++) {
        float b = sB[tc + 16 * i];
#pragma unroll
        for (int r = 0; r < 8; r++) {
            unsigned lo, hi;
            UNPACK2(lo, hi, acc[r][i]);
            float a = __uint_as_float(lo) + __uint_as_float(hi) + b;
            if (RELU) a = fmaxf(a, 0.0f);
            sOut[(tr * 8 + r) * HDIM + tc + 16 * i] = a;
        }
    }
}

__global__ void __launch_bounds__(NTHR, 2) mlp_kernel(
    const float* __restrict__ obs, const float* __restrict__ gp,
    const float* __restrict__ W1, const float* __restrict__ b1,
    const float* __restrict__ W2, const float* __restrict__ b2,
    const float* __restrict__ W3, const float* __restrict__ b3,
    const float* __restrict__ cW1, const float* __restrict__ cb1,
    const float* __restrict__ cW2, const float* __restrict__ cb2,
    const float* __restrict__ cW3, const float* __restrict__ cb3,
    float* __restrict__ out) {
    float* sW1T = smem + OFF_W1T;
    float* sW2T = smem + OFF_W2T;
    float* sW3T = smem + OFF_W3T;
    float* sVW  = smem + OFF_VW;
    float* sB1  = smem + OFF_B1;
    float* sB2  = smem + OFF_B2;
    float* sB3  = smem + OFF_B3;
    float* sVB  = smem + OFF_VB;
    float* sX   = smem + OFF_X;
    float* sH1  = smem + OFF_H1;
    float* sH2  = sX;  // reuse X buffer after layer 1 (stride HDIM)
    int*   sRows = (int*)(smem + OFF_ROWS);

    const int tid = threadIdx.x;
    const int c = blockIdx.x;
    const bool critic = (c >= 4 * ECTAS);

    int e = 0, j, tstride, ntiles;
    if (!critic) {
        e = c / ECTAS;
        j = c - e * ECTAS;
        tstride = ECTAS;
        ntiles = (g_cnt[e] + TILE - 1) / TILE;
    } else {
        j = c - 4 * ECTAS;
        tstride = NCTA - 4 * ECTAS;   // 148
        ntiles = TA / TILE;           // 2048
    }

    // ---- stage weights ONCE (transposed) ----
    if (!critic) {
        const float* w1p = W1 + (size_t)e * DIN * HDIM;
        const float* w2p = W2 + (size_t)e * HDIM * HDIM;
        const float* w3p = W3 + (size_t)e * HDIM * NA;
        for (int i = tid; i < DIN * HDIM; i += NTHR) {
            int k = i >> 6, cc = i & 63;
            sW1T[cc * WS1 + k] = w1p[i];
        }
        for (int i = tid; i < HDIM * HDIM; i += NTHR) {
            int k = i >> 6, cc = i & 63;
            sW2T[cc * WS + k] = w2p[i];
        }
        for (int i = tid; i < HDIM * NA; i += NTHR) {
            int k = i >> 4, cc = i & 15;
            sW3T[cc * WS + k] = w3p[i];
        }
        if (tid < HDIM) { sB1[tid] = b1[e * HDIM + tid]; sB2[tid] = b2[e * HDIM + tid]; }
        if (tid < NA) sB3[tid] = b3[e * NA + tid];
    } else {
        for (int i = tid; i < DIN * HDIM; i += NTHR) {
            int k = i >> 6, cc = i & 63;
            sW1T[cc * WS1 + k] = cW1[i];
        }
        for (int i = tid; i < HDIM * HDIM; i += NTHR) {
            int k = i >> 6, cc = i & 63;
            sW2T[cc * WS + k] = cW2[i];
        }
        if (tid < HDIM) { sVW[tid] = cW3[tid]; sB1[tid] = cb1[tid]; sB2[tid] = cb2[tid]; }
        if (tid == 0) sVB[0] = cb3[0];
    }

    const int cnt = critic ? TA : g_cnt[e];

    // ---- persistent tile loop ----
    for (int t = j; t < ntiles; t += tstride) {
        const int start = t * TILE;
        const int nvalid = min(TILE, cnt - start);

        __syncthreads();   // protect sX/sH2/sRows reuse (also covers weight staging on iter 0)

        if (tid < TILE) {
            int row;
            if (critic) row = start + tid;
            else row = (tid < nvalid) ? g_perm[e * TA + start + tid] : 0;
            sRows[tid] = row;
        }
        __syncthreads();

        // stage X tile: [r][0..63] = obs row, [r][64..67] = gp_sel_summary[t_env]
        for (int idx = tid; idx < TILE * 16; idx += NTHR) {
            int r = idx >> 4, q = idx & 15;
            float4 v = *(const float4*)(obs + (size_t)sRows[r] * D_OBS + q * 4);
            *(float4*)&sX[r * DIN + q * 4] = v;
        }
        if (tid < TILE) {
            int tenv = sRows[tid] >> 7;   // row / 128 agents
            *(float4*)&sX[tid * DIN + D_OBS] = *(const float4*)(gp + tenv * NTP);
        }
        __syncthreads();

        layerT<DIN, DIN, WS1, true>(sX, sW1T, sB1, sH1, tid);
        __syncthreads();
        layerT<HDIM, HDIM, WS, true>(sH1, sW2T, sB2, sH2, tid);
        __syncthreads();

        if (!critic) {
            // logits: thread = col cc (0..15) x 8 rows; k-parity f32x2 lanes
            const int cc = tid & 15;
            const int r0 = (tid >> 4) * 8;
            u64 acc[8];
#pragma unroll
            for (int r = 0; r < 8; r++) acc[r] = 0ull;
            const float* wrow = sW3T + cc * WS;
            for (int k = 0; k < HDIM; k += 4) {
                u64 w01 = *(const u64*)&wrow[k];
                u64 w23 = *(const u64*)&wrow[k + 2];
#pragma unroll
                for (int r = 0; r < 8; r++) {
                    ulonglong2 h = *(const ulonglong2*)&sH2[(r0 + r) * HDIM + k];
                    FMA2(acc[r], h.x, w01);
                    FMA2(acc[r], h.y, w23);
                }
            }
            float bc = sB3[cc];
#pragma unroll
            for (int r = 0; r < 8; r++) {
                unsigned lo, hi;
                UNPACK2(lo, hi, acc[r]);
                float a = __uint_as_float(lo) + __uint_as_float(hi) + bc;
                if (r0 + r < nvalid)
                    out[(size_t)sRows[r0 + r] * OUTC + cc] = a;
            }
        } else {
            // value column: 2 threads per row
            const int r = tid >> 1;
            const int p = tid & 1;
            u64 acc = 0ull;
            for (int kk = 0; kk < 32; kk += 4) {
                int k = p * 32 + kk;
                ulonglong2 h = *(const ulonglong2*)&sH2[r * HDIM + k];
                ulonglong2 w = *(const ulonglong2*)&sVW[k];
                FMA2(acc, h.x, w.x);
                FMA2(acc, h.y, w.y);
            }
            unsigned lo, hi;
            UNPACK2(lo, hi, acc);
            float a = __uint_as_float(lo) + __uint_as_float(hi);
            a += __shfl_xor_sync(0xffffffffu, a, 1);
            if (p == 0)
                out[(size_t)(start + r) * OUTC + NA] = a + sVB[0];
        }
    }
}

// ---------------- launch ----------------
extern "C" void kernel_launch(void* const* d_in, const int* in_sizes, int n_in,
                              void* d_out, int out_size) {
    const float* obs  = (const float*)d_in[0];
    const int*   hete = (const int*)d_in[1];
    const float* gp   = (const float*)d_in[2];
    const float* W1   = (const float*)d_in[3];
    const float* b1   = (const float*)d_in[4];
    const float* W2   = (const float*)d_in[5];
    const float* b2   = (const float*)d_in[6];
    const float* W3   = (const float*)d_in[7];
    const float* b3   = (const float*)d_in[8];
    const float* cW1  = (const float*)d_in[9];
    const float* cb1  = (const float*)d_in[10];
    const float* cW2  = (const float*)d_in[11];
    const float* cb2  = (const float*)d_in[12];
    const float* cW3  = (const float*)d_in[13];
    const float* cb3  = (const float*)d_in[14];
    float* out = (float*)d_out;

    cudaFuncSetAttribute(mlp_kernel, cudaFuncAttributeMaxDynamicSharedMemorySize,
                         SMEM_BYTES);

    k_init<<<1, 32>>>();
    k_detect<<<128, 256>>>(hete);
    k_build<<<TA / 512, 512>>>(hete);

    mlp_kernel<<<NCTA, NTHR, SMEM_BYTES>>>(obs, gp, W1, b1, W2, b2, W3, b3,
                                           cW1, cb1, cW2, cb2, cW3, cb3, out);
}

// round 4
// speedup vs baseline: 1.4720x; 1.1669x over previous
#include <cuda_runtime.h>
#include <cstddef>

// Problem constants
#define TA      262144      // T*A = 2048*128
#define D_OBS   64
#define NTP     4
#define DIN     68          // D_OBS + NTP
#define HDIM    64
#define NA      16
#define OUTC    17          // NA + 1 (value)
#define TILE    128         // rows per tile
#define NTHR    256
#define NCTA    296         // persistent CTAs (2 per SM on 148 SMs)
#define ECTAS   37          // CTAs per expert (4*37 = 148)
#define LDX     68          // row stride for X/H tiles: 17 x 16B (odd) -> conflict-free

// ---------------- scratch ----------------
__device__ int g_perm[NTP * TA];   // per-expert buckets at base e*TA
__device__ int g_cnt[NTP];
__device__ int g_flag;             // 1 => hete_pick stored as int32, 0 => int64

// ---------------- f32x2 helpers ----------------
#define FMA2(acc, a, b) \
    asm("fma.rn.f32x2 %0, %1, %2, %0;" : "+l"(acc) : "l"(a), "l"(b))
#define PACK_DUP(d, x) \
    asm("mov.b64 %0, {%1, %1};" : "=l"(d) : "r"(__float_as_uint(x)))
#define UNPACK2(lo, hi, v) \
    asm("mov.b64 {%0, %1}, %2;" : "=r"(lo), "=r"(hi) : "l"(v))

typedef unsigned long long u64;

// ---------------- prologue kernels ----------------
__global__ void k_init() {
    int t = threadIdx.x;
    if (t < NTP) g_cnt[t] = 0;
    if (t == NTP) g_flag = 0;
}

// Detect int32 vs int64 storage of hete_pick (int64 LE: odd words all zero).
__global__ void k_detect(const int* __restrict__ h) {
    int stride = gridDim.x * blockDim.x;
    int acc = 0;
    for (int j = blockIdx.x * blockDim.x + threadIdx.x; j < TA / 2; j += stride)
        acc |= h[2 * j + 1];
    unsigned any = __ballot_sync(0xffffffffu, acc != 0);
    if ((threadIdx.x & 31) == 0 && any) atomicOr(&g_flag, 1);
}

__device__ __forceinline__ int pick_at(const int* __restrict__ h, int i, int f) {
    return f ? h[i] : h[2 * i];
}

// Block-aggregated classify+scatter into per-expert buckets.
__global__ void k_build(const int* __restrict__ h) {
    __shared__ int sHist[NTP], sBase[NTP], sRank[NTP];
    int tid = threadIdx.x;
    if (tid < NTP) { sHist[tid] = 0; sRank[tid] = 0; }
    __syncthreads();
    int f = g_flag;
    int i = blockIdx.x * 512 + tid;
    int t = pick_at(h, i, f);
    atomicAdd(&sHist[t], 1);
    __syncthreads();
    if (tid < NTP) sBase[tid] = atomicAdd(&g_cnt[tid], sHist[tid]);
    __syncthreads();
    int p = atomicAdd(&sRank[t], 1);
    g_perm[t * TA + sBase[t] + p] = i;
}

// ---------------- shared layout (floats) ----------------
// Weights stay in native k-major layout: W[k][c].
#define OFF_W1   0                          // [68][64]
#define OFF_W2   (OFF_W1 + DIN * HDIM)      // 4352  [64][64]
#define OFF_W3   (OFF_W2 + HDIM * HDIM)     // 8448  [64][16]
#define OFF_VW   (OFF_W3 + HDIM * NA)       // 9472  critic W3 vector [64]
#define OFF_B1   (OFF_VW + 64)              // 9536
#define OFF_B2   (OFF_B1 + 64)              // 9600
#define OFF_B3   (OFF_B2 + 64)              // 9664
#define OFF_VB   (OFF_B3 + 16)              // 9680
#define OFF_X    (OFF_VB + 4)               // 9684  [128][68]
#define OFF_H1   (OFF_X + TILE * LDX)       // 18388 [128][68]
#define OFF_ROWS (OFF_H1 + TILE * LDX)      // 27092 (ints)
#define SMEM_FLOATS (OFF_ROWS + TILE)       // 27220
#define SMEM_BYTES  (SMEM_FLOATS * 4)       // 108880

extern __shared__ float smem[];

// out[128][64] = act(in[128][KD] @ W + b). W in native k-major smem: sW[k][c].
// Warp wid owns cols c0=wid*8 (4 f32x2 col-pairs) for ALL rows -> W loads are
// warp-uniform (smem broadcast). Thread = rows {lane, lane+32, lane+64, lane+96}.
template <int KD, bool RELU>
__device__ __forceinline__ void layer64(const float* __restrict__ sIn,
                                        const float* __restrict__ sW,
                                        const float* __restrict__ sB,
                                        float* __restrict__ sOut, int tid) {
    const int lane = tid & 31;
    const int c0 = (tid >> 5) * 8;
    u64 acc[4][4];
#pragma unroll
    for (int j = 0; j < 4; j++)
#pragma unroll
        for (int p = 0; p < 4; p++) acc[j][p] = 0ull;

    for (int k = 0; k < KD; k += 4) {
        float4 xv[4];
#pragma unroll
        for (int j = 0; j < 4; j++)
            xv[j] = *(const float4*)&sIn[(lane + 32 * j) * LDX + k];
#pragma unroll
        for (int kk = 0; kk < 4; kk++) {
            const float* wr = sW + (k + kk) * HDIM + c0;
            ulonglong2 wlo = *(const ulonglong2*)&wr[0];   // pairs (c0,c0+1),(c0+2,c0+3)
            ulonglong2 whi = *(const ulonglong2*)&wr[4];   // pairs (c0+4..7)
#pragma unroll
            for (int j = 0; j < 4; j++) {
                float xs = (kk == 0) ? xv[j].x : (kk == 1) ? xv[j].y
                         : (kk == 2) ? xv[j].z : xv[j].w;
                u64 bx;
                PACK_DUP(bx, xs);
                FMA2(acc[j][0], bx, wlo.x);
                FMA2(acc[j][1], bx, wlo.y);
                FMA2(acc[j][2], bx, whi.x);
                FMA2(acc[j][3], bx, whi.y);
            }
        }
    }

    float4 blo = *(const float4*)&sB[c0];
    float4 bhi = *(const float4*)&sB[c0 + 4];
#pragma unroll
    for (int j = 0; j < 4; j++) {
        int row = lane + 32 * j;
        float o[8];
#pragma unroll
        for (int p = 0; p < 4; p++) {
            unsigned lo, hi;
            UNPACK2(lo, hi, acc[j][p]);
            o[2 * p] = __uint_as_float(lo);
            o[2 * p + 1] = __uint_as_float(hi);
        }
        o[0] += blo.x; o[1] += blo.y; o[2] += blo.z; o[3] += blo.w;
        o[4] += bhi.x; o[5] += bhi.y; o[6] += bhi.z; o[7] += bhi.w;
        if (RELU) {
#pragma unroll
            for (int q = 0; q < 8; q++) o[q] = fmaxf(o[q], 0.0f);
        }
        float4 v0 = make_float4(o[0], o[1], o[2], o[3]);
        float4 v1 = make_float4(o[4], o[5], o[6], o[7]);
        *(float4*)&sOut[row * LDX + c0] = v0;
        *(float4*)&sOut[row * LDX + c0 + 4] = v1;
    }
}

__global__ void __launch_bounds__(NTHR, 2) mlp_kernel(
    const float* __restrict__ obs, const float* __restrict__ gp,
    const float* __restrict__ W1, const float* __restrict__ b1,
    const float* __restrict__ W2, const float* __restrict__ b2,
    const float* __restrict__ W3, const float* __restrict__ b3,
    const float* __restrict__ cW1, const float* __restrict__ cb1,
    const float* __restrict__ cW2, const float* __restrict__ cb2,
    const float* __restrict__ cW3, const float* __restrict__ cb3,
    float* __restrict__ out) {
    float* sW1 = smem + OFF_W1;
    float* sW2 = smem + OFF_W2;
    float* sW3 = smem + OFF_W3;
    float* sVW = smem + OFF_VW;
    float* sB1 = smem + OFF_B1;
    float* sB2 = smem + OFF_B2;
    float* sB3 = smem + OFF_B3;
    float* sVB = smem + OFF_VB;
    float* sX  = smem + OFF_X;
    float* sH1 = smem + OFF_H1;
    float* sH2 = sX;  // reuse X buffer after layer 1 (stride LDX)
    int*   sRows = (int*)(smem + OFF_ROWS);

    const int tid = threadIdx.x;
    const int c = blockIdx.x;
    const bool critic = (c >= 4 * ECTAS);

    int e = 0, j0, tstride, ntiles;
    if (!critic) {
        e = c / ECTAS;
        j0 = c - e * ECTAS;
        tstride = ECTAS;
        ntiles = (g_cnt[e] + TILE - 1) / TILE;
    } else {
        j0 = c - 4 * ECTAS;
        tstride = NCTA - 4 * ECTAS;   // 148
        ntiles = TA / TILE;           // 2048
    }

    // ---- stage weights ONCE (native layout: straight copy) ----
    {
        const float* w1p = critic ? cW1 : (W1 + (size_t)e * DIN * HDIM);
        const float* w2p = critic ? cW2 : (W2 + (size_t)e * HDIM * HDIM);
        for (int i = tid; i < DIN * HDIM / 4; i += NTHR)
            ((float4*)sW1)[i] = ((const float4*)w1p)[i];
        for (int i = tid; i < HDIM * HDIM / 4; i += NTHR)
            ((float4*)sW2)[i] = ((const float4*)w2p)[i];
        if (!critic) {
            const float* w3p = W3 + (size_t)e * HDIM * NA;
            for (int i = tid; i < HDIM * NA / 4; i += NTHR)
                ((float4*)sW3)[i] = ((const float4*)w3p)[i];
            if (tid < HDIM) { sB1[tid] = b1[e * HDIM + tid]; sB2[tid] = b2[e * HDIM + tid]; }
            if (tid < NA) sB3[tid] = b3[e * NA + tid];
        } else {
            if (tid < HDIM) { sVW[tid] = cW3[tid]; sB1[tid] = cb1[tid]; sB2[tid] = cb2[tid]; }
            if (tid == 0) sVB[0] = cb3[0];
        }
    }

    const int cnt = critic ? TA : g_cnt[e];

    // ---- persistent tile loop ----
    for (int t = j0; t < ntiles; t += tstride) {
        const int start = t * TILE;
        const int nvalid = min(TILE, cnt - start);

        __syncthreads();   // protect sX/sH2/sRows reuse (covers staging on iter 0)

        if (tid < TILE) {
            int row;
            if (critic) row = start + tid;
            else row = (tid < nvalid) ? g_perm[e * TA + start + tid] : 0;
            sRows[tid] = row;
        }
        __syncthreads();

        // stage X tile: [r][0..63] = obs row, [r][64..67] = gp_sel_summary
        for (int idx = tid; idx < TILE * 16; idx += NTHR) {
            int r = idx >> 4, q = idx & 15;
            float4 v = *(const float4*)(obs + (size_t)sRows[r] * D_OBS + q * 4);
            *(float4*)&sX[r * LDX + q * 4] = v;
        }
        if (tid < TILE) {
            int tenv = sRows[tid] >> 7;   // row / 128 agents
            *(float4*)&sX[tid * LDX + D_OBS] = *(const float4*)(gp + tenv * NTP);
        }
        __syncthreads();

        layer64<DIN, true>(sX, sW1, sB1, sH1, tid);
        __syncthreads();
        layer64<HDIM, true>(sH1, sW2, sB2, sH2, tid);
        __syncthreads();

        if (!critic) {
            // logits 128x16: warp owns col-pair (2*wid, 2*wid+1); thread = 4 rows.
            const int lane = tid & 31;
            const int cp = (tid >> 5) * 2;   // first col of pair
            u64 acc[4];
#pragma unroll
            for (int j = 0; j < 4; j++) acc[j] = 0ull;
            for (int k = 0; k < HDIM; k += 4) {
                float4 xv[4];
#pragma unroll
                for (int j = 0; j < 4; j++)
                    xv[j] = *(const float4*)&sH2[(lane + 32 * j) * LDX + k];
#pragma unroll
                for (int kk = 0; kk < 4; kk++) {
                    u64 w = *(const u64*)&sW3[(k + kk) * NA + cp];  // broadcast
#pragma unroll
                    for (int j = 0; j < 4; j++) {
                        float xs = (kk == 0) ? xv[j].x : (kk == 1) ? xv[j].y
                                 : (kk == 2) ? xv[j].z : xv[j].w;
                        u64 bx;
                        PACK_DUP(bx, xs);
                        FMA2(acc[j], bx, w);
                    }
                }
            }
            float bc0 = sB3[cp], bc1 = sB3[cp + 1];
#pragma unroll
            for (int j = 0; j < 4; j++) {
                int r = lane + 32 * j;
                unsigned lo, hi;
                UNPACK2(lo, hi, acc[j]);
                if (r < nvalid) {
                    size_t o = (size_t)sRows[r] * OUTC + cp;
                    out[o] = __uint_as_float(lo) + bc0;
                    out[o + 1] = __uint_as_float(hi) + bc1;
                }
            }
        } else {
            // value column: 2 threads per row, k-parity f32x2
            const int r = tid >> 1;
            const int p = tid & 1;
            u64 acc = 0ull;
            for (int kk = 0; kk < 32; kk += 4) {
                int k = p * 32 + kk;
                ulonglong2 h = *(const ulonglong2*)&sH2[r * LDX + k];
                ulonglong2 w = *(const ulonglong2*)&sVW[k];
                FMA2(acc, h.x, w.x);
                FMA2(acc, h.y, w.y);
            }
            unsigned lo, hi;
            UNPACK2(lo, hi, acc);
            float a = __uint_as_float(lo) + __uint_as_float(hi);
            a += __shfl_xor_sync(0xffffffffu, a, 1);
            if (p == 0)
                out[(size_t)(start + r) * OUTC + NA] = a + sVB[0];
        }
    }
}

// ---------------- launch ----------------
extern "C" void kernel_launch(void* const* d_in, const int* in_sizes, int n_in,
                              void* d_out, int out_size) {
    const float* obs  = (const float*)d_in[0];
    const int*   hete = (const int*)d_in[1];
    const float* gp   = (const float*)d_in[2];
    const float* W1   = (const float*)d_in[3];
    const float* b1   = (const float*)d_in[4];
    const float* W2   = (const float*)d_in[5];
    const float* b2   = (const float*)d_in[6];
    const float* W3   = (const float*)d_in[7];
    const float* b3   = (const float*)d_in[8];
    const float* cW1  = (const float*)d_in[9];
    const float* cb1  = (const float*)d_in[10];
    const float* cW2  = (const float*)d_in[11];
    const float* cb2  = (const float*)d_in[12];
    const float* cW3  = (const float*)d_in[13];
    const float* cb3  = (const float*)d_in[14];
    float* out = (float*)d_out;

    cudaFuncSetAttribute(mlp_kernel, cudaFuncAttributeMaxDynamicSharedMemorySize,
                         SMEM_BYTES);

    k_init<<<1, 32>>>();
    k_detect<<<128, 256>>>(hete);
    k_build<<<TA / 512, 512>>>(hete);

    mlp_kernel<<<NCTA, NTHR, SMEM_BYTES>>>(obs, gp, W1, b1, W2, b2, W3, b3,
                                           cW1, cb1, cW2, cb2, cW3, cb3, out);
}

// round 5
// speedup vs baseline: 1.4728x; 1.0005x over previous
#include <cuda_runtime.h>
#include <cstddef>

// Problem constants
#define TA      262144      // T*A = 2048*128
#define D_OBS   64
#define NTP     4
#define DIN     68          // D_OBS + NTP
#define HDIM    64
#define NA      16
#define OUTC    17          // NA + 1 (value)
#define TILE    128         // rows per tile
#define NTHR    256
#define NCTA    296         // persistent CTAs (2 per SM on 148 SMs)
#define ECTAS   37          // CTAs per expert (4*37 = 148)
#define LDX     68          // row stride for X/H tiles (8 consecutive rows -> 32 banks)

// ---------------- scratch ----------------
__device__ int g_perm[NTP * TA];   // per-expert buckets at base e*TA
__device__ int g_cnt[NTP];
__device__ int g_flag;             // 1 => hete_pick stored as int32, 0 => int64

// ---------------- f32x2 helpers ----------------
#define FMA2(acc, a, b) \
    asm("fma.rn.f32x2 %0, %1, %2, %0;" : "+l"(acc) : "l"(a), "l"(b))
#define PACK_DUP(d, x) \
    asm("mov.b64 %0, {%1, %1};" : "=l"(d) : "r"(__float_as_uint(x)))
#define UNPACK2(lo, hi, v) \
    asm("mov.b64 {%0, %1}, %2;" : "=r"(lo), "=r"(hi) : "l"(v))

typedef unsigned long long u64;

// ---------------- prologue kernels ----------------
__global__ void k_init() {
    int t = threadIdx.x;
    if (t < NTP) g_cnt[t] = 0;
    if (t == NTP) g_flag = 0;
}

// Detect int32 vs int64 storage of hete_pick (int64 LE: odd words all zero).
__global__ void k_detect(const int* __restrict__ h) {
    int stride = gridDim.x * blockDim.x;
    int acc = 0;
    for (int j = blockIdx.x * blockDim.x + threadIdx.x; j < TA / 2; j += stride)
        acc |= h[2 * j + 1];
    unsigned any = __ballot_sync(0xffffffffu, acc != 0);
    if ((threadIdx.x & 31) == 0 && any) atomicOr(&g_flag, 1);
}

__device__ __forceinline__ int pick_at(const int* __restrict__ h, int i, int f) {
    return f ? h[i] : h[2 * i];
}

// Block-aggregated classify+scatter into per-expert buckets.
__global__ void k_build(const int* __restrict__ h) {
    __shared__ int sHist[NTP], sBase[NTP], sRank[NTP];
    int tid = threadIdx.x;
    if (tid < NTP) { sHist[tid] = 0; sRank[tid] = 0; }
    __syncthreads();
    int f = g_flag;
    int i = blockIdx.x * 512 + tid;
    int t = pick_at(h, i, f);
    atomicAdd(&sHist[t], 1);
    __syncthreads();
    if (tid < NTP) sBase[tid] = atomicAdd(&g_cnt[tid], sHist[tid]);
    __syncthreads();
    int p = atomicAdd(&sRank[t], 1);
    g_perm[t * TA + sBase[t] + p] = i;
}

// ---------------- shared layout (floats) ----------------
#define OFF_W1   0                          // [68][64] k-major
#define OFF_W2   (OFF_W1 + DIN * HDIM)      // 4352  [64][64]
#define OFF_W3   (OFF_W2 + HDIM * HDIM)     // 8448  [64][16]
#define OFF_VW   (OFF_W3 + HDIM * NA)       // 9472  critic W3 vector [64]
#define OFF_B1   (OFF_VW + 64)              // 9536
#define OFF_B2   (OFF_B1 + 64)              // 9600
#define OFF_B3   (OFF_B2 + 64)              // 9664
#define OFF_VB   (OFF_B3 + 16)              // 9680
#define OFF_X    (OFF_VB + 4)               // 9684  [128][68]
#define OFF_H1   (OFF_X + TILE * LDX)       // 18388 [128][68]
#define OFF_ROWS (OFF_H1 + TILE * LDX)      // 27092 (ints)
#define SMEM_FLOATS (OFF_ROWS + TILE)       // 27220
#define SMEM_BYTES  (SMEM_FLOATS * 4)       // 108880

extern __shared__ float smem[];

// out[128][64] = act(in[128][KD] @ W + b). W native k-major smem: sW[k][c].
// Warp = 32-row group x 32-col half; thread = rows {rg*32+8j+lr} x cols
// {ch*32+cg*8 .. +7}. X LDS.128 hits 8 consecutive rows -> 1 wavefront,
// conflict-free; W LDS.128 hits 4 distinct 16B chunks -> 1 wavefront.
template <int KD, bool RELU>
__device__ __forceinline__ void layer64(const float* __restrict__ sIn,
                                        const float* __restrict__ sW,
                                        const float* __restrict__ sB,
                                        float* __restrict__ sOut, int tid) {
    const int lane = tid & 31;
    const int warp = tid >> 5;
    const int rbase = (warp >> 1) * 32 + (lane & 7);   // + 8j
    const int c0 = (warp & 1) * 32 + (lane >> 3) * 8;

    u64 acc[4][4];
#pragma unroll
    for (int j = 0; j < 4; j++)
#pragma unroll
        for (int p = 0; p < 4; p++) acc[j][p] = 0ull;

    for (int k = 0; k < KD; k += 4) {
        float4 xv[4];
#pragma unroll
        for (int j = 0; j < 4; j++)
            xv[j] = *(const float4*)&sIn[(rbase + 8 * j) * LDX + k];
#pragma unroll
        for (int kk = 0; kk < 4; kk++) {
            const float* wr = sW + (k + kk) * HDIM + c0;
            ulonglong2 wlo = *(const ulonglong2*)&wr[0];
            ulonglong2 whi = *(const ulonglong2*)&wr[4];
#pragma unroll
            for (int j = 0; j < 4; j++) {
                float xs = (kk == 0) ? xv[j].x : (kk == 1) ? xv[j].y
                         : (kk == 2) ? xv[j].z : xv[j].w;
                u64 bx;
                PACK_DUP(bx, xs);
                FMA2(acc[j][0], bx, wlo.x);
                FMA2(acc[j][1], bx, wlo.y);
                FMA2(acc[j][2], bx, whi.x);
                FMA2(acc[j][3], bx, whi.y);
            }
        }
    }

    float4 blo = *(const float4*)&sB[c0];
    float4 bhi = *(const float4*)&sB[c0 + 4];
#pragma unroll
    for (int j = 0; j < 4; j++) {
        int row = rbase + 8 * j;
        float o[8];
#pragma unroll
        for (int p = 0; p < 4; p++) {
            unsigned lo, hi;
            UNPACK2(lo, hi, acc[j][p]);
            o[2 * p] = __uint_as_float(lo);
            o[2 * p + 1] = __uint_as_float(hi);
        }
        o[0] += blo.x; o[1] += blo.y; o[2] += blo.z; o[3] += blo.w;
        o[4] += bhi.x; o[5] += bhi.y; o[6] += bhi.z; o[7] += bhi.w;
        if (RELU) {
#pragma unroll
            for (int q = 0; q < 8; q++) o[q] = fmaxf(o[q], 0.0f);
        }
        *(float4*)&sOut[row * LDX + c0] = make_float4(o[0], o[1], o[2], o[3]);
        *(float4*)&sOut[row * LDX + c0 + 4] = make_float4(o[4], o[5], o[6], o[7]);
    }
}

__global__ void __launch_bounds__(NTHR, 2) mlp_kernel(
    const float* __restrict__ obs, const float* __restrict__ gp,
    const float* __restrict__ W1, const float* __restrict__ b1,
    const float* __restrict__ W2, const float* __restrict__ b2,
    const float* __restrict__ W3, const float* __restrict__ b3,
    const float* __restrict__ cW1, const float* __restrict__ cb1,
    const float* __restrict__ cW2, const float* __restrict__ cb2,
    const float* __restrict__ cW3, const float* __restrict__ cb3,
    float* __restrict__ out) {
    float* sW1 = smem + OFF_W1;
    float* sW2 = smem + OFF_W2;
    float* sW3 = smem + OFF_W3;
    float* sVW = smem + OFF_VW;
    float* sB1 = smem + OFF_B1;
    float* sB2 = smem + OFF_B2;
    float* sB3 = smem + OFF_B3;
    float* sVB = smem + OFF_VB;
    float* sX  = smem + OFF_X;
    float* sH1 = smem + OFF_H1;
    float* sH2 = sX;  // reuse X buffer after layer 1 (stride LDX)
    int*   sRows = (int*)(smem + OFF_ROWS);

    const int tid = threadIdx.x;
    const int c = blockIdx.x;
    const bool critic = (c >= 4 * ECTAS);

    int e = 0, j0, tstride, ntiles;
    if (!critic) {
        e = c / ECTAS;
        j0 = c - e * ECTAS;
        tstride = ECTAS;
        ntiles = (g_cnt[e] + TILE - 1) / TILE;
    } else {
        j0 = c - 4 * ECTAS;
        tstride = NCTA - 4 * ECTAS;   // 148
        ntiles = TA / TILE;           // 2048
    }

    // ---- stage weights ONCE (native layout: straight copy) ----
    {
        const float* w1p = critic ? cW1 : (W1 + (size_t)e * DIN * HDIM);
        const float* w2p = critic ? cW2 : (W2 + (size_t)e * HDIM * HDIM);
        for (int i = tid; i < DIN * HDIM / 4; i += NTHR)
            ((float4*)sW1)[i] = ((const float4*)w1p)[i];
        for (int i = tid; i < HDIM * HDIM / 4; i += NTHR)
            ((float4*)sW2)[i] = ((const float4*)w2p)[i];
        if (!critic) {
            const float* w3p = W3 + (size_t)e * HDIM * NA;
            for (int i = tid; i < HDIM * NA / 4; i += NTHR)
                ((float4*)sW3)[i] = ((const float4*)w3p)[i];
            if (tid < HDIM) { sB1[tid] = b1[e * HDIM + tid]; sB2[tid] = b2[e * HDIM + tid]; }
            if (tid < NA) sB3[tid] = b3[e * NA + tid];
        } else {
            if (tid < HDIM) { sVW[tid] = cW3[tid]; sB1[tid] = cb1[tid]; sB2[tid] = cb2[tid]; }
            if (tid == 0) sVB[0] = cb3[0];
        }
    }

    const int cnt = critic ? TA : g_cnt[e];

    // ---- persistent tile loop ----
    for (int t = j0; t < ntiles; t += tstride) {
        const int start = t * TILE;
        const int nvalid = min(TILE, cnt - start);

        __syncthreads();   // protect sX/sH2/sRows reuse (covers staging on iter 0)

        if (tid < TILE) {
            int row;
            if (critic) row = start + tid;
            else row = (tid < nvalid) ? g_perm[e * TA + start + tid] : 0;
            sRows[tid] = row;
        }
        __syncthreads();

        // stage X tile: [r][0..63] = obs row, [r][64..67] = gp_sel_summary
        for (int idx = tid; idx < TILE * 16; idx += NTHR) {
            int r = idx >> 4, q = idx & 15;
            float4 v = *(const float4*)(obs + (size_t)sRows[r] * D_OBS + q * 4);
            *(float4*)&sX[r * LDX + q * 4] = v;
        }
        if (tid < TILE) {
            int tenv = sRows[tid] >> 7;   // row / 128 agents
            *(float4*)&sX[tid * LDX + D_OBS] = *(const float4*)(gp + tenv * NTP);
        }
        __syncthreads();

        layer64<DIN, true>(sX, sW1, sB1, sH1, tid);
        __syncthreads();
        layer64<HDIM, true>(sH1, sW2, sB2, sH2, tid);
        __syncthreads();

        if (!critic) {
            // logits 128x16: warp = 32-row group x 8-col half; thread = 4 rows,
            // 1 f32x2 col-pair. W3 loads: 4 distinct 8B -> 1 wavefront.
            const int lane = tid & 31;
            const int warp = tid >> 5;
            const int rbase = (warp >> 1) * 32 + (lane & 7);
            const int cp = (warp & 1) * 8 + (lane >> 3) * 2;
            u64 acc[4];
#pragma unroll
            for (int j = 0; j < 4; j++) acc[j] = 0ull;
            for (int k = 0; k < HDIM; k += 4) {
                float4 xv[4];
#pragma unroll
                for (int j = 0; j < 4; j++)
                    xv[j] = *(const float4*)&sH2[(rbase + 8 * j) * LDX + k];
#pragma unroll
                for (int kk = 0; kk < 4; kk++) {
                    u64 w = *(const u64*)&sW3[(k + kk) * NA + cp];
#pragma unroll
                    for (int j = 0; j < 4; j++) {
                        float xs = (kk == 0) ? xv[j].x : (kk == 1) ? xv[j].y
                                 : (kk == 2) ? xv[j].z : xv[j].w;
                        u64 bx;
                        PACK_DUP(bx, xs);
                        FMA2(acc[j], bx, w);
                    }
                }
            }
            float bc0 = sB3[cp], bc1 = sB3[cp + 1];
#pragma unroll
            for (int j = 0; j < 4; j++) {
                int r = rbase + 8 * j;
                unsigned lo, hi;
                UNPACK2(lo, hi, acc[j]);
                if (r < nvalid) {
                    size_t o = (size_t)sRows[r] * OUTC + cp;
                    out[o] = __uint_as_float(lo) + bc0;
                    out[o + 1] = __uint_as_float(hi) + bc1;
                }
            }
        } else {
            // value column: 2 threads per row, k-parity f32x2
            const int r = tid >> 1;
            const int p = tid & 1;
            u64 acc = 0ull;
            for (int kk = 0; kk < 32; kk += 4) {
                int k = p * 32 + kk;
                ulonglong2 h = *(const ulonglong2*)&sH2[r * LDX + k];
                ulonglong2 w = *(const ulonglong2*)&sVW[k];
                FMA2(acc, h.x, w.x);
                FMA2(acc, h.y, w.y);
            }
            unsigned lo, hi;
            UNPACK2(lo, hi, acc);
            float a = __uint_as_float(lo) + __uint_as_float(hi);
            a += __shfl_xor_sync(0xffffffffu, a, 1);
            if (p == 0)
                out[(size_t)(start + r) * OUTC + NA] = a + sVB[0];
        }
    }
}

// ---------------- launch ----------------
extern "C" void kernel_launch(void* const* d_in, const int* in_sizes, int n_in,
                              void* d_out, int out_size) {
    const float* obs  = (const float*)d_in[0];
    const int*   hete = (const int*)d_in[1];
    const float* gp   = (const float*)d_in[2];
    const float* W1   = (const float*)d_in[3];
    const float* b1   = (const float*)d_in[4];
    const float* W2   = (const float*)d_in[5];
    const float* b2   = (const float*)d_in[6];
    const float* W3   = (const float*)d_in[7];
    const float* b3   = (const float*)d_in[8];
    const float* cW1  = (const float*)d_in[9];
    const float* cb1  = (const float*)d_in[10];
    const float* cW2  = (const float*)d_in[11];
    const float* cb2  = (const float*)d_in[12];
    const float* cW3  = (const float*)d_in[13];
    const float* cb3  = (const float*)d_in[14];
    float* out = (float*)d_out;

    cudaFuncSetAttribute(mlp_kernel, cudaFuncAttributeMaxDynamicSharedMemorySize,
                         SMEM_BYTES);

    k_init<<<1, 32>>>();
    k_detect<<<128, 256>>>(hete);
    k_build<<<TA / 512, 512>>>(hete);

    mlp_kernel<<<NCTA, NTHR, SMEM_BYTES>>>(obs, gp, W1, b1, W2, b2, W3, b3,
                                           cW1, cb1, cW2, cb2, cW3, cb3, out);
}